// round 1
// baseline (speedup 1.0000x reference)
#include <cuda_runtime.h>

#define Bq 8
#define Tq 4096
#define DINq 1024
#define DMq 256
#define NCq 157

// Scratch (allocation-free: __device__ globals)
__device__ float g_out[Bq * DMq * Tq];
__device__ float g_q  [Bq * DMq * Tq];
__device__ float g_k  [Bq * DMq * Tq];
__device__ float g_v  [Bq * DMq * Tq];
__device__ float g_h  [Bq * DMq * Tq];

// ---------------------------------------------------------------------------
// SGEMM: C[b,o,t] = sum_i W[o,i] * X[b,i,t]  (+ epilogue)
// EPI: 0 = plain, 1 = +bias, 2 = +bias, +residual, *mask (in-place on C),
//      3 = +bias, *mask
// Tile: 128(M=o) x 128(N=t) x 16(K=i), 256 threads, 8x8 microtile.
// ---------------------------------------------------------------------------
template <int EPI>
__global__ __launch_bounds__(256, 2)
void sgemm_kernel(const float* __restrict__ W, const float* __restrict__ X,
                  const float* __restrict__ bias, const float* __restrict__ mask,
                  float* __restrict__ C, const float* __restrict__ R,
                  int O, int I)
{
    const int bT = blockIdx.x * 128;
    const int bO = blockIdx.y * 128;
    const int b  = blockIdx.z;

    const float* Xb = X + (size_t)b * I * Tq;

    __shared__ float Ws[16][132];   // padded: stride 132 (132%32==4) to reduce conflicts
    __shared__ float Xs[16][128];

    const int tid = threadIdx.x;
    const int tx = tid & 15;        // n-group
    const int ty = tid >> 4;        // m-group

    float acc[8][8];
#pragma unroll
    for (int i = 0; i < 8; i++)
#pragma unroll
        for (int j = 0; j < 8; j++) acc[i][j] = 0.f;

    // W-load mapping: each thread loads 2 float4 along K
    const int wm = tid >> 2;          // 0..63 (+64 on rep 1)
    const int wk = (tid & 3) * 4;     // 0,4,8,12
    // X-load mapping: each thread loads 2 float4 along T
    const int xr = tid >> 5;          // 0..7 (+8 on rep 1)
    const int xn = (tid & 31) * 4;    // 0..124

    for (int k0 = 0; k0 < I; k0 += 16) {
#pragma unroll
        for (int rep = 0; rep < 2; rep++) {
            const int m = wm + rep * 64;
            const int o = bO + m;
            float4 w4;
            if (o < O) w4 = *(const float4*)(W + (size_t)o * I + k0 + wk);
            else       w4 = make_float4(0.f, 0.f, 0.f, 0.f);
            Ws[wk + 0][m] = w4.x;
            Ws[wk + 1][m] = w4.y;
            Ws[wk + 2][m] = w4.z;
            Ws[wk + 3][m] = w4.w;
        }
#pragma unroll
        for (int rep = 0; rep < 2; rep++) {
            const int r = xr + rep * 8;
            *(float4*)&Xs[r][xn] =
                *(const float4*)(Xb + (size_t)(k0 + r) * Tq + bT + xn);
        }
        __syncthreads();

#pragma unroll
        for (int k = 0; k < 16; k++) {
            float a[8], x[8];
            *(float4*)&a[0] = *(const float4*)&Ws[k][ty * 4];
            *(float4*)&a[4] = *(const float4*)&Ws[k][64 + ty * 4];
            *(float4*)&x[0] = *(const float4*)&Xs[k][tx * 4];
            *(float4*)&x[4] = *(const float4*)&Xs[k][64 + tx * 4];
#pragma unroll
            for (int i = 0; i < 8; i++)
#pragma unroll
                for (int j = 0; j < 8; j++)
                    acc[i][j] = fmaf(a[i], x[j], acc[i][j]);
        }
        __syncthreads();
    }

    // ---- epilogue ----
    int mrow[8], ncol[8];
#pragma unroll
    for (int i = 0; i < 8; i++) mrow[i] = (i < 4) ? (ty * 4 + i) : (64 + ty * 4 + i - 4);
#pragma unroll
    for (int j = 0; j < 8; j++) ncol[j] = (j < 4) ? (tx * 4 + j) : (64 + tx * 4 + j - 4);

    float bvals[8];
#pragma unroll
    for (int i = 0; i < 8; i++) {
        const int o = bO + mrow[i];
        bvals[i] = (EPI >= 1 && o < O) ? bias[o] : 0.f;
    }

    float mv[8];
    if (EPI >= 2) {
#pragma unroll
        for (int j = 0; j < 8; j++)
            mv[j] = mask[(size_t)b * Tq + bT + ncol[j]];
    }

    float*       Cb = C + (size_t)b * O * Tq;
    const float* Rb = (EPI == 2) ? (R + (size_t)b * O * Tq) : nullptr;

#pragma unroll
    for (int i = 0; i < 8; i++) {
        const int o = bO + mrow[i];
        if (o >= O) continue;
        const size_t rowoff = (size_t)o * Tq + bT;
#pragma unroll
        for (int j = 0; j < 8; j++) {
            float val = acc[i][j] + bvals[i];
            if (EPI == 2) val = (Rb[rowoff + ncol[j]] + val) * mv[j];
            if (EPI == 3) val = val * mv[j];
            Cb[rowoff + ncol[j]] = val;
        }
    }
}

// ---------------------------------------------------------------------------
// Dilated 3-tap attention (pointwise) + ReLU.
// Out-of-range taps contribute k=0, v=0 but DO participate in the softmax
// (score 0), matching the zero-padded reference exactly.
// ---------------------------------------------------------------------------
__global__ __launch_bounds__(256)
void dal_attn_kernel(const float* __restrict__ q, const float* __restrict__ k,
                     const float* __restrict__ v, float* __restrict__ h, int d)
{
    const int row = blockIdx.y;                      // b*DM + c
    const int t   = blockIdx.x * 256 + threadIdx.x;  // 0..T-1
    const size_t base = (size_t)row * Tq;

    const float qv = q[base + t];
    const float k0 = (t - d >= 0) ? k[base + t - d] : 0.f;
    const float k1 = k[base + t];
    const float k2 = (t + d < Tq) ? k[base + t + d] : 0.f;
    const float v0 = (t - d >= 0) ? v[base + t - d] : 0.f;
    const float v1 = v[base + t];
    const float v2 = (t + d < Tq) ? v[base + t + d] : 0.f;

    const float s0 = qv * k0, s1 = qv * k1, s2 = qv * k2;
    const float mx = fmaxf(s0, fmaxf(s1, s2));
    const float e0 = __expf(s0 - mx);
    const float e1 = __expf(s1 - mx);
    const float e2 = __expf(s2 - mx);
    const float inv = 1.f / (e0 + e1 + e2);
    const float o = (e0 * v0 + e1 * v1 + e2 * v2) * inv;
    h[base + t] = fmaxf(o, 0.f);   // ReLU fused here
}

// ---------------------------------------------------------------------------
// Launch
// Input order: 0 x, 1 mask, 2 b0w, 3 b0b,
//   per layer l=1..5: (4+5(l-1)) wq, wk, wv, bw, bb
//   29 b6w, 30 b6b
// ---------------------------------------------------------------------------
extern "C" void kernel_launch(void* const* d_in, const int* in_sizes, int n_in,
                              void* d_out, int out_size)
{
    const float* x    = (const float*)d_in[0];
    const float* mask = (const float*)d_in[1];
    const float* b0w  = (const float*)d_in[2];
    const float* b0b  = (const float*)d_in[3];
    const float* b6w  = (const float*)d_in[29];
    const float* b6b  = (const float*)d_in[30];

    float *out, *q, *k, *v, *h;
    cudaGetSymbolAddress((void**)&out, g_out);
    cudaGetSymbolAddress((void**)&q,   g_q);
    cudaGetSymbolAddress((void**)&k,   g_k);
    cudaGetSymbolAddress((void**)&v,   g_v);
    cudaGetSymbolAddress((void**)&h,   g_h);

    const dim3 thr(256);
    const dim3 g_dm (Tq / 128, (DMq + 127) / 128, Bq);   // (32, 2, 8)
    const dim3 g_nc (Tq / 128, (NCq + 127) / 128, Bq);   // (32, 2, 8)
    const dim3 g_at (Tq / 256, Bq * DMq);                // (16, 2048)

    // out = bottle0_w @ x + bottle0_b
    sgemm_kernel<1><<<g_dm, thr>>>(b0w, x, b0b, nullptr, out, nullptr, DMq, DINq);

    const int dils[5] = {1, 2, 4, 8, 16};
    for (int l = 0; l < 5; l++) {
        const float* wq = (const float*)d_in[4 + 5 * l + 0];
        const float* wk = (const float*)d_in[4 + 5 * l + 1];
        const float* wv = (const float*)d_in[4 + 5 * l + 2];
        const float* bw = (const float*)d_in[4 + 5 * l + 3];
        const float* bb = (const float*)d_in[4 + 5 * l + 4];

        sgemm_kernel<0><<<g_dm, thr>>>(wq, out, nullptr, nullptr, q, nullptr, DMq, DMq);
        sgemm_kernel<0><<<g_dm, thr>>>(wk, out, nullptr, nullptr, k, nullptr, DMq, DMq);
        sgemm_kernel<0><<<g_dm, thr>>>(wv, out, nullptr, nullptr, v, nullptr, DMq, DMq);

        dal_attn_kernel<<<g_at, thr>>>(q, k, v, h, dils[l]);

        // out = (out + bw@h + bb) * mask   (in-place residual)
        sgemm_kernel<2><<<g_dm, thr>>>(bw, h, bb, mask, out, out, DMq, DMq);
    }

    // final: (b6w @ out + b6b) * mask
    sgemm_kernel<3><<<g_nc, thr>>>(b6w, out, b6b, mask, (float*)d_out, nullptr, NCq, DMq);
}

// round 3
// speedup vs baseline: 1.4486x; 1.4486x over previous
#include <cuda_runtime.h>
#include <cuda_bf16.h>

#define Bq   8
#define Tq   4096
#define DINq 1024
#define DMq  256
#define NCq  157

// ---------------------------------------------------------------------------
// Scratch (fp32, [B, T, C] layout — K-major for the MMA B operand)
// ---------------------------------------------------------------------------
__device__ float g_xt [Bq * Tq * DINq];
__device__ float g_out[Bq * Tq * DMq];
__device__ float g_q  [Bq * Tq * DMq];
__device__ float g_k  [Bq * Tq * DMq];
__device__ float g_v  [Bq * Tq * DMq];
__device__ float g_h  [Bq * Tq * DMq];

// ---------------------------------------------------------------------------
// Helpers
// ---------------------------------------------------------------------------
__device__ __forceinline__ unsigned smem_u32(const void* p) {
    unsigned a;
    asm("{ .reg .u64 t; cvta.to.shared.u64 t, %1; cvt.u32.u64 %0, t; }" : "=r"(a) : "l"(p));
    return a;
}

// split x,y into bf16 hi pair + lo pair (packed, x in low half = lower k)
__device__ __forceinline__ void split2(float x, float y, unsigned& hi, unsigned& lo) {
    __nv_bfloat16 hx = __float2bfloat16_rn(x);
    __nv_bfloat16 hy = __float2bfloat16_rn(y);
    __nv_bfloat16 lx = __float2bfloat16_rn(x - __bfloat162float(hx));
    __nv_bfloat16 ly = __float2bfloat16_rn(y - __bfloat162float(hy));
    hi = (unsigned)__bfloat16_as_ushort(hx) | ((unsigned)__bfloat16_as_ushort(hy) << 16);
    lo = (unsigned)__bfloat16_as_ushort(lx) | ((unsigned)__bfloat16_as_ushort(ly) << 16);
}

__device__ __forceinline__ void ldmat4(unsigned (&r)[4], unsigned addr) {
    asm volatile("ldmatrix.sync.aligned.m8n8.x4.shared.b16 {%0,%1,%2,%3}, [%4];"
                 : "=r"(r[0]), "=r"(r[1]), "=r"(r[2]), "=r"(r[3]) : "r"(addr));
}

__device__ __forceinline__ void mma16816(float (&c)[4], const unsigned (&a)[4],
                                         unsigned b0, unsigned b1) {
    asm volatile(
        "mma.sync.aligned.m16n8k16.row.col.f32.bf16.bf16.f32 "
        "{%0,%1,%2,%3}, {%4,%5,%6,%7}, {%8,%9}, {%0,%1,%2,%3};"
        : "+f"(c[0]), "+f"(c[1]), "+f"(c[2]), "+f"(c[3])
        : "r"(a[0]), "r"(a[1]), "r"(a[2]), "r"(a[3]), "r"(b0), "r"(b1));
}

// ---------------------------------------------------------------------------
// GEMM: D[o,t] = sum_i W[o,i] * Act[b,t,i]   (split-bf16, mma.sync)
// Block 128(M=o) x 128(N=t), K-chunk 32, 256 threads (8 warps, 4m x 2n),
// warp tile 32x64. Double-buffered smem, 80B row stride (conflict-free).
// EPI: 0 plain, 1 +bias, 2 (resid+D+bias)*mask  -> fp32 [b,t,o]
//      3 (D+bias)*mask -> fp32 [b,o,t]
// ---------------------------------------------------------------------------
#define TILE_LO   10240              // 128 rows * 80B  (hi part size)
#define TILE_SZ   20480              // hi + lo
#define STAGE_SZ  40960              // A tile + B tile
#define SMEM_TOT  81920              // 2 stages

template <int EPI, int KTOT, int OROWS>
__global__ void __launch_bounds__(256, 2)
gemm_mma(const float* __restrict__ W, const float* __restrict__ Act,
         const float* __restrict__ bias, const float* __restrict__ mask,
         const float* __restrict__ resid, float* __restrict__ Out)
{
    extern __shared__ char smem[];
    const unsigned sb = smem_u32(smem);
    const int tid  = threadIdx.x;
    const int lane = tid & 31, wid = tid >> 5;
    const int bT = blockIdx.x * 128;
    const int bO = blockIdx.y * 128;
    const int b  = blockIdx.z;
    const int m0 = (wid & 3) * 32;       // warp m offset
    const int n0 = (wid >> 2) * 64;      // warp n offset

    constexpr bool GUARDA = (OROWS & 127) != 0;

    const float* Bg = Act + ((size_t)b * Tq + bT) * KTOT;

    // per-thread ldmatrix intra-tile offsets
    const int la = (lane & 15) * 80 + (lane >> 4) * 16;
    const int matv = lane >> 3;
    const int lb = ((lane & 7) + ((matv >> 1) * 8)) * 80 + ((matv & 1) * 16);

    float acc[2][8][4];
#pragma unroll
    for (int i = 0; i < 2; i++)
#pragma unroll
        for (int j = 0; j < 8; j++)
#pragma unroll
            for (int l = 0; l < 4; l++) acc[i][j][l] = 0.f;

    float4 ra[4], rb[4];

    // ---- tile load (global -> regs) ----
    auto loadA = [&](float4 (&r)[4], int k0) {
#pragma unroll
        for (int it = 0; it < 4; it++) {
            const int task = it * 256 + tid;
            const int rr = task >> 3, c4 = task & 7;
            if (GUARDA && (bO + rr >= OROWS)) r[it] = make_float4(0.f, 0.f, 0.f, 0.f);
            else r[it] = *(const float4*)(W + (size_t)(bO + rr) * KTOT + k0 + c4 * 4);
        }
    };
    auto loadB = [&](float4 (&r)[4], int k0) {
#pragma unroll
        for (int it = 0; it < 4; it++) {
            const int task = it * 256 + tid;
            const int rr = task >> 3, c4 = task & 7;
            r[it] = *(const float4*)(Bg + (size_t)rr * KTOT + k0 + c4 * 4);
        }
    };
    // ---- tile store (regs -> smem hi/lo bf16) ----
    auto stTile = [&](const float4 (&r)[4], char* dst) {
#pragma unroll
        for (int it = 0; it < 4; it++) {
            const int task = it * 256 + tid;
            const int rr = task >> 3, c4 = task & 7;
            unsigned h0, l0, h1, l1;
            split2(r[it].x, r[it].y, h0, l0);
            split2(r[it].z, r[it].w, h1, l1);
            char* p = dst + rr * 80 + c4 * 8;
            *(uint2*)(p)           = make_uint2(h0, h1);
            *(uint2*)(p + TILE_LO) = make_uint2(l0, l1);
        }
    };

    constexpr int NCH = KTOT / 32;

    loadA(ra, 0);
    loadB(rb, 0);
    stTile(ra, smem);
    stTile(rb, smem + TILE_SZ);

#pragma unroll 1
    for (int ch = 0; ch < NCH; ch++) {
        __syncthreads();
        const unsigned Ab = sb + (ch & 1) * STAGE_SZ;
        const unsigned Bb = Ab + TILE_SZ;

        if (ch + 1 < NCH) {
            loadA(ra, (ch + 1) * 32);
            loadB(rb, (ch + 1) * 32);
        }

#pragma unroll
        for (int combo = 0; combo < 3; combo++) {
            const unsigned Asel = Ab + ((combo == 2) ? TILE_LO : 0);
            const unsigned Bsel = Bb + ((combo == 1) ? TILE_LO : 0);
#pragma unroll
            for (int kk = 0; kk < 2; kk++) {
                unsigned aU[2][4];
#pragma unroll
                for (int mi = 0; mi < 2; mi++)
                    ldmat4(aU[mi], Asel + (m0 + mi * 16) * 80 + la + kk * 32);
#pragma unroll
                for (int nt2 = 0; nt2 < 4; nt2++) {
                    unsigned bU[4];
                    ldmat4(bU, Bsel + (n0 + nt2 * 16) * 80 + lb + kk * 32);
                    mma16816(acc[0][nt2 * 2 + 0], aU[0], bU[0], bU[1]);
                    mma16816(acc[0][nt2 * 2 + 1], aU[0], bU[2], bU[3]);
                    mma16816(acc[1][nt2 * 2 + 0], aU[1], bU[0], bU[1]);
                    mma16816(acc[1][nt2 * 2 + 1], aU[1], bU[2], bU[3]);
                }
            }
        }

        if (ch + 1 < NCH) {
            char* nb = smem + ((ch + 1) & 1) * STAGE_SZ;
            stTile(ra, nb);
            stTile(rb, nb + TILE_SZ);
        }
    }

    // ---- epilogue ----
    const int g = lane >> 2, tig = lane & 3;
#pragma unroll
    for (int mi = 0; mi < 2; mi++) {
#pragma unroll
        for (int pr = 0; pr < 2; pr++) {
            const int o = bO + m0 + mi * 16 + g + pr * 8;
            float bs = 0.f;
            if (EPI >= 1) bs = (!GUARDA || o < OROWS) ? bias[o] : 0.f;
#pragma unroll
            for (int nt = 0; nt < 8; nt++) {
                const int t = bT + n0 + nt * 8 + 2 * tig;
                float v0 = acc[mi][nt][pr * 2 + 0] + bs;
                float v1 = acc[mi][nt][pr * 2 + 1] + bs;
                if (EPI == 3) {
                    if (!GUARDA || o < OROWS) {
                        const float mk0 = mask[(size_t)b * Tq + t];
                        const float mk1 = mask[(size_t)b * Tq + t + 1];
                        float2 w = make_float2(v0 * mk0, v1 * mk1);
                        *(float2*)(Out + ((size_t)b * OROWS + o) * Tq + t) = w;
                    }
                } else {
                    const size_t i0 = ((size_t)b * Tq + t) * DMq + o;
                    if (EPI == 2) {
                        const float mk0 = mask[(size_t)b * Tq + t];
                        const float mk1 = mask[(size_t)b * Tq + t + 1];
                        v0 = (resid[i0]       + v0) * mk0;
                        v1 = (resid[i0 + DMq] + v1) * mk1;
                    }
                    Out[i0]       = v0;
                    Out[i0 + DMq] = v1;
                }
            }
        }
    }
}

// ---------------------------------------------------------------------------
// x transpose: [B, DIN, T] -> [B, T, DIN] fp32
// ---------------------------------------------------------------------------
__global__ __launch_bounds__(256)
void xpose_kernel(const float* __restrict__ x, float* __restrict__ xt)
{
    __shared__ float s[32][33];
    const int t0 = blockIdx.x * 32, i0 = blockIdx.y * 32, b = blockIdx.z;
    const int tx = threadIdx.x & 31, ty = threadIdx.x >> 5;
    const float* xb = x + (size_t)b * DINq * Tq;
#pragma unroll
    for (int kk = 0; kk < 4; kk++)
        s[ty + 8 * kk][tx] = xb[(size_t)(i0 + ty + 8 * kk) * Tq + t0 + tx];
    __syncthreads();
    float* xtb = xt + (size_t)b * Tq * DINq;
#pragma unroll
    for (int kk = 0; kk < 4; kk++)
        xtb[(size_t)(t0 + ty + 8 * kk) * DINq + i0 + tx] = s[tx][ty + 8 * kk];
}

// ---------------------------------------------------------------------------
// Dilated 3-tap softmax attention + ReLU on [B, T, C] fp32, float4 over C
// ---------------------------------------------------------------------------
__device__ __forceinline__ float attn1(float q, float k0, float k1, float k2,
                                       float v0, float v1, float v2)
{
    const float s0 = q * k0, s1 = q * k1, s2 = q * k2;
    const float mx = fmaxf(s0, fmaxf(s1, s2));
    const float e0 = __expf(s0 - mx), e1 = __expf(s1 - mx), e2 = __expf(s2 - mx);
    return fmaxf((e0 * v0 + e1 * v1 + e2 * v2) / (e0 + e1 + e2), 0.f);
}

__global__ __launch_bounds__(256)
void attn_kernel(const float4* __restrict__ q, const float4* __restrict__ k,
                 const float4* __restrict__ v, float4* __restrict__ h, int d)
{
    const size_t gid = (size_t)blockIdx.x * 256 + threadIdx.x;  // float4 index
    const int t = (int)((gid >> 6) & (Tq - 1));
    const long long off = (long long)d * (DMq / 4);

    const float4 qv = q[gid];
    const float4 k1 = k[gid];
    const float4 v1 = v[gid];
    float4 k0 = make_float4(0.f, 0.f, 0.f, 0.f), v0 = k0, k2 = k0, v2 = k0;
    if (t - d >= 0) { k0 = k[gid - off]; v0 = v[gid - off]; }
    if (t + d < Tq) { k2 = k[gid + off]; v2 = v[gid + off]; }

    float4 r;
    r.x = attn1(qv.x, k0.x, k1.x, k2.x, v0.x, v1.x, v2.x);
    r.y = attn1(qv.y, k0.y, k1.y, k2.y, v0.y, v1.y, v2.y);
    r.z = attn1(qv.z, k0.z, k1.z, k2.z, v0.z, v1.z, v2.z);
    r.w = attn1(qv.w, k0.w, k1.w, k2.w, v0.w, v1.w, v2.w);
    h[gid] = r;
}

// ---------------------------------------------------------------------------
// Launch
// ---------------------------------------------------------------------------
extern "C" void kernel_launch(void* const* d_in, const int* in_sizes, int n_in,
                              void* d_out, int out_size)
{
    const float* x    = (const float*)d_in[0];
    const float* mask = (const float*)d_in[1];
    const float* b0w  = (const float*)d_in[2];
    const float* b0b  = (const float*)d_in[3];
    const float* b6w  = (const float*)d_in[29];
    const float* b6b  = (const float*)d_in[30];

    float *xt, *out, *q, *k, *v, *h;
    cudaGetSymbolAddress((void**)&xt,  g_xt);
    cudaGetSymbolAddress((void**)&out, g_out);
    cudaGetSymbolAddress((void**)&q,   g_q);
    cudaGetSymbolAddress((void**)&k,   g_k);
    cudaGetSymbolAddress((void**)&v,   g_v);
    cudaGetSymbolAddress((void**)&h,   g_h);

    cudaFuncSetAttribute(gemm_mma<1, DINq, DMq>, cudaFuncAttributeMaxDynamicSharedMemorySize, SMEM_TOT);
    cudaFuncSetAttribute(gemm_mma<0, DMq,  DMq>, cudaFuncAttributeMaxDynamicSharedMemorySize, SMEM_TOT);
    cudaFuncSetAttribute(gemm_mma<2, DMq,  DMq>, cudaFuncAttributeMaxDynamicSharedMemorySize, SMEM_TOT);
    cudaFuncSetAttribute(gemm_mma<3, DMq,  NCq>, cudaFuncAttributeMaxDynamicSharedMemorySize, SMEM_TOT);

    // transpose input
    xpose_kernel<<<dim3(Tq / 32, DINq / 32, Bq), 256>>>(x, xt);

    const dim3 thr(256);
    const dim3 g_dm(Tq / 128, DMq / 128, Bq);                  // (32, 2, 8)
    const dim3 g_nc(Tq / 128, (NCq + 127) / 128, Bq);          // (32, 2, 8)
    const int  g_at = (Bq * Tq * DMq / 4) / 256;               // 8192

    // input GEMM: out = b0w @ xt + b0b
    gemm_mma<1, DINq, DMq><<<g_dm, thr, SMEM_TOT>>>(b0w, xt, b0b, nullptr, nullptr, out);

    const int dils[5] = {1, 2, 4, 8, 16};
    for (int l = 0; l < 5; l++) {
        const float* wq = (const float*)d_in[4 + 5 * l + 0];
        const float* wk = (const float*)d_in[4 + 5 * l + 1];
        const float* wv = (const float*)d_in[4 + 5 * l + 2];
        const float* bw = (const float*)d_in[4 + 5 * l + 3];
        const float* bb = (const float*)d_in[4 + 5 * l + 4];

        gemm_mma<0, DMq, DMq><<<g_dm, thr, SMEM_TOT>>>(wq, out, nullptr, nullptr, nullptr, q);
        gemm_mma<0, DMq, DMq><<<g_dm, thr, SMEM_TOT>>>(wk, out, nullptr, nullptr, nullptr, k);
        gemm_mma<0, DMq, DMq><<<g_dm, thr, SMEM_TOT>>>(wv, out, nullptr, nullptr, nullptr, v);

        attn_kernel<<<g_at, thr>>>((const float4*)q, (const float4*)k,
                                   (const float4*)v, (float4*)h, dils[l]);

        gemm_mma<2, DMq, DMq><<<g_dm, thr, SMEM_TOT>>>(bw, h, bb, mask, out, out);
    }

    // final: (b6w @ out + b6b) * mask -> fp32 [B, NC, T]
    gemm_mma<3, DMq, NCq><<<g_nc, thr, SMEM_TOT>>>(b6w, out, b6b, mask, nullptr, (float*)d_out);
}

// round 4
// speedup vs baseline: 1.7837x; 1.2313x over previous
#include <cuda_runtime.h>
#include <cuda_bf16.h>

#define Bq   8
#define Tq   4096
#define DINq 1024
#define DMq  256
#define NCq  157

// ---------------------------------------------------------------------------
// Scratch: activations as separate bf16 hi/lo arrays, layout [B, T, C]
// value = float(hi) + float(lo)  (error ~2^-18 relative)
// ---------------------------------------------------------------------------
__device__ __nv_bfloat16 g_xh [Bq * Tq * DINq];
__device__ __nv_bfloat16 g_xl [Bq * Tq * DINq];
__device__ __nv_bfloat16 g_oh [Bq * Tq * DMq];
__device__ __nv_bfloat16 g_ol [Bq * Tq * DMq];
__device__ __nv_bfloat16 g_qh [Bq * Tq * DMq];
__device__ __nv_bfloat16 g_ql [Bq * Tq * DMq];
__device__ __nv_bfloat16 g_kh [Bq * Tq * DMq];
__device__ __nv_bfloat16 g_kl [Bq * Tq * DMq];
__device__ __nv_bfloat16 g_vh [Bq * Tq * DMq];
__device__ __nv_bfloat16 g_vl [Bq * Tq * DMq];
__device__ __nv_bfloat16 g_hh [Bq * Tq * DMq];
__device__ __nv_bfloat16 g_hl [Bq * Tq * DMq];

// Weights split hi/lo, packed: b0w(256x1024), 20x(256x256), b6w(157x256)
#define W_B0    0
#define W_L0    262144
#define W_PERL  (4 * 65536)
#define W_B6    (262144 + 5 * W_PERL)
#define W_TOTAL (W_B6 + NCq * DMq)          // 1,613,056
__device__ __nv_bfloat16 g_wh[W_TOTAL];
__device__ __nv_bfloat16 g_wl[W_TOTAL];

// ---------------------------------------------------------------------------
// Helpers
// ---------------------------------------------------------------------------
__device__ __forceinline__ unsigned smem_u32(const void* p) {
    unsigned a;
    asm("{ .reg .u64 t; cvta.to.shared.u64 t, %1; cvt.u32.u64 %0, t; }" : "=r"(a) : "l"(p));
    return a;
}
__device__ __forceinline__ void split1(float v, __nv_bfloat16& h, __nv_bfloat16& l) {
    h = __float2bfloat16_rn(v);
    l = __float2bfloat16_rn(v - __bfloat162float(h));
}
__device__ __forceinline__ void ldmat4(unsigned (&r)[4], unsigned addr) {
    asm volatile("ldmatrix.sync.aligned.m8n8.x4.shared.b16 {%0,%1,%2,%3}, [%4];"
                 : "=r"(r[0]), "=r"(r[1]), "=r"(r[2]), "=r"(r[3]) : "r"(addr));
}
__device__ __forceinline__ void mma16816(float (&c)[4], const unsigned (&a)[4],
                                         unsigned b0, unsigned b1) {
    asm volatile(
        "mma.sync.aligned.m16n8k16.row.col.f32.bf16.bf16.f32 "
        "{%0,%1,%2,%3}, {%4,%5,%6,%7}, {%8,%9}, {%0,%1,%2,%3};"
        : "+f"(c[0]), "+f"(c[1]), "+f"(c[2]), "+f"(c[3])
        : "r"(a[0]), "r"(a[1]), "r"(a[2]), "r"(a[3]), "r"(b0), "r"(b1));
}
__device__ __forceinline__ void cp16(unsigned saddr, const void* gaddr, int srcsz) {
    asm volatile("cp.async.ca.shared.global [%0], [%1], 16, %2;"
                 :: "r"(saddr), "l"(gaddr), "r"(srcsz) : "memory");
}
#define CP_COMMIT() asm volatile("cp.async.commit_group;" ::: "memory")
#define CP_WAIT0()  asm volatile("cp.async.wait_group 0;" ::: "memory")

// ---------------------------------------------------------------------------
// GEMM: D[o,t] = sum_i W[o,i] * Act[b,t,i]   (split-bf16 x3, mma.sync)
// Block 128(M=o) x 128(N=t), K-chunk 32, 256 threads (8 warps, 4m x 2n),
// warp tile 32x64. cp.async double-buffered, 80B row stride.
// EPI: 0 plain, 1 +bias, 2 (resid+D+bias)*mask -> bf16 hi/lo [b,t,o]
//      3 (D+bias)*mask -> fp32 [b,o,t]
// ---------------------------------------------------------------------------
#define TILE_P  10240               // one 128x32 bf16 part (80B stride)
#define STAGE   40960               // A.hi A.lo B.hi B.lo
#define SMEM_TOT 81920

template <int EPI, int KTOT, int OROWS>
__global__ void __launch_bounds__(256, 2)
gemm_mma(const __nv_bfloat16* __restrict__ Whi, const __nv_bfloat16* __restrict__ Wlo,
         const __nv_bfloat16* __restrict__ Ahi, const __nv_bfloat16* __restrict__ Alo,
         const float* __restrict__ bias, const float* __restrict__ mask,
         const __nv_bfloat16* __restrict__ Rhi, const __nv_bfloat16* __restrict__ Rlo,
         __nv_bfloat16* __restrict__ Ohi, __nv_bfloat16* __restrict__ Olo,
         float* __restrict__ OF)
{
    extern __shared__ char smem[];
    const unsigned sb = smem_u32(smem);
    const int tid  = threadIdx.x;
    const int lane = tid & 31, wid = tid >> 5;
    const int bT = blockIdx.x * 128;
    const int bO = blockIdx.y * 128;
    const int b  = blockIdx.z;
    const int m0 = (wid & 3) * 32;
    const int n0 = (wid >> 2) * 64;

    constexpr bool GUARDA = (OROWS & 127) != 0;
    constexpr int NCH = KTOT / 32;

    const __nv_bfloat16* Bh = Ahi + ((size_t)b * Tq + bT) * KTOT;
    const __nv_bfloat16* Bl = Alo + ((size_t)b * Tq + bT) * KTOT;

    // ldmatrix per-thread offsets (80B row stride)
    const int la = (lane & 15) * 80 + (lane >> 4) * 16;
    const int matv = lane >> 3;
    const int lb = ((lane & 7) + ((matv >> 1) * 8)) * 80 + ((matv & 1) * 16);

    float acc[2][8][4];
#pragma unroll
    for (int i = 0; i < 2; i++)
#pragma unroll
        for (int j = 0; j < 8; j++)
#pragma unroll
            for (int l = 0; l < 4; l++) acc[i][j][l] = 0.f;

    // ---- async tile issue: 8 cp.async/thread (A.hi A.lo B.hi B.lo) ----
    auto issue = [&](int ch) {
        const int k0 = ch * 32;
        const unsigned st = sb + (ch & 1) * STAGE;
#pragma unroll
        for (int i = 0; i < 2; i++) {
            const int c = i * 256 + tid;
            const int row = c >> 2, c4 = c & 3;
            const unsigned soff = (unsigned)(row * 80 + c4 * 16);
            int asz = 16;
            size_t aoff = (size_t)(bO + row) * KTOT + k0 + c4 * 8;
            if (GUARDA && (bO + row >= OROWS)) { asz = 0; aoff = 0; }
            cp16(st + soff,              Whi + aoff, asz);
            cp16(st + TILE_P + soff,     Wlo + aoff, asz);
            const size_t boff = (size_t)row * KTOT + k0 + c4 * 8;
            cp16(st + 2 * TILE_P + soff, Bh + boff, 16);
            cp16(st + 3 * TILE_P + soff, Bl + boff, 16);
        }
        CP_COMMIT();
    };

    issue(0);

#pragma unroll 1
    for (int ch = 0; ch < NCH; ch++) {
        CP_WAIT0();
        __syncthreads();
        if (ch + 1 < NCH) issue(ch + 1);

        const unsigned Ah_ = sb + (ch & 1) * STAGE;
        const unsigned Al_ = Ah_ + TILE_P;
        const unsigned Bh_ = Ah_ + 2 * TILE_P;
        const unsigned Bl_ = Ah_ + 3 * TILE_P;

#pragma unroll
        for (int kk = 0; kk < 2; kk++) {
            unsigned ah[2][4], al[2][4];
            ldmat4(ah[0], Ah_ + (m0     ) * 80 + la + kk * 32);
            ldmat4(ah[1], Ah_ + (m0 + 16) * 80 + la + kk * 32);
            ldmat4(al[0], Al_ + (m0     ) * 80 + la + kk * 32);
            ldmat4(al[1], Al_ + (m0 + 16) * 80 + la + kk * 32);
#pragma unroll
            for (int nt2 = 0; nt2 < 4; nt2++) {
                unsigned bh[4], bl[4];
                ldmat4(bh, Bh_ + (n0 + nt2 * 16) * 80 + lb + kk * 32);
                ldmat4(bl, Bl_ + (n0 + nt2 * 16) * 80 + lb + kk * 32);
                // hi*hi
                mma16816(acc[0][nt2 * 2 + 0], ah[0], bh[0], bh[1]);
                mma16816(acc[0][nt2 * 2 + 1], ah[0], bh[2], bh[3]);
                mma16816(acc[1][nt2 * 2 + 0], ah[1], bh[0], bh[1]);
                mma16816(acc[1][nt2 * 2 + 1], ah[1], bh[2], bh[3]);
                // hi*lo
                mma16816(acc[0][nt2 * 2 + 0], ah[0], bl[0], bl[1]);
                mma16816(acc[0][nt2 * 2 + 1], ah[0], bl[2], bl[3]);
                mma16816(acc[1][nt2 * 2 + 0], ah[1], bl[0], bl[1]);
                mma16816(acc[1][nt2 * 2 + 1], ah[1], bl[2], bl[3]);
                // lo*hi
                mma16816(acc[0][nt2 * 2 + 0], al[0], bh[0], bh[1]);
                mma16816(acc[0][nt2 * 2 + 1], al[0], bh[2], bh[3]);
                mma16816(acc[1][nt2 * 2 + 0], al[1], bh[0], bh[1]);
                mma16816(acc[1][nt2 * 2 + 1], al[1], bh[2], bh[3]);
            }
        }
    }

    // ---- epilogue ----
    const int g = lane >> 2, tig = lane & 3;
#pragma unroll
    for (int mi = 0; mi < 2; mi++) {
#pragma unroll
        for (int pr = 0; pr < 2; pr++) {
            const int o = bO + m0 + mi * 16 + g + pr * 8;
            float bs = 0.f;
            if (EPI >= 1) bs = (!GUARDA || o < OROWS) ? bias[o] : 0.f;
#pragma unroll
            for (int nt = 0; nt < 8; nt++) {
                const int t = bT + n0 + nt * 8 + 2 * tig;
                float v0 = acc[mi][nt][pr * 2 + 0] + bs;
                float v1 = acc[mi][nt][pr * 2 + 1] + bs;
                if (EPI == 3) {
                    if (!GUARDA || o < OROWS) {
                        const float mk0 = mask[(size_t)b * Tq + t];
                        const float mk1 = mask[(size_t)b * Tq + t + 1];
                        *(float2*)(OF + ((size_t)b * OROWS + o) * Tq + t) =
                            make_float2(v0 * mk0, v1 * mk1);
                    }
                } else {
                    const size_t i0 = ((size_t)b * Tq + t) * DMq + o;
                    if (EPI == 2) {
                        const float mk0 = mask[(size_t)b * Tq + t];
                        const float mk1 = mask[(size_t)b * Tq + t + 1];
                        float r0 = __bfloat162float(Rhi[i0]) + __bfloat162float(Rlo[i0]);
                        float r1 = __bfloat162float(Rhi[i0 + DMq]) + __bfloat162float(Rlo[i0 + DMq]);
                        v0 = (r0 + v0) * mk0;
                        v1 = (r1 + v1) * mk1;
                    }
                    __nv_bfloat16 h0, l0, h1, l1;
                    split1(v0, h0, l0);
                    split1(v1, h1, l1);
                    Ohi[i0] = h0; Olo[i0] = l0;
                    Ohi[i0 + DMq] = h1; Olo[i0 + DMq] = l1;
                }
            }
        }
    }
}

// ---------------------------------------------------------------------------
// x transpose + split: [B, DIN, T] fp32 -> [B, T, DIN] bf16 hi/lo
// ---------------------------------------------------------------------------
__global__ __launch_bounds__(256)
void xpose_kernel(const float* __restrict__ x,
                  __nv_bfloat16* __restrict__ xh, __nv_bfloat16* __restrict__ xl)
{
    __shared__ float s[32][33];
    const int t0 = blockIdx.x * 32, i0 = blockIdx.y * 32, b = blockIdx.z;
    const int tx = threadIdx.x & 31, ty = threadIdx.x >> 5;
    const float* xb = x + (size_t)b * DINq * Tq;
#pragma unroll
    for (int kk = 0; kk < 4; kk++)
        s[ty + 8 * kk][tx] = xb[(size_t)(i0 + ty + 8 * kk) * Tq + t0 + tx];
    __syncthreads();
#pragma unroll
    for (int kk = 0; kk < 4; kk++) {
        const float v = s[tx][ty + 8 * kk];
        const size_t idx = ((size_t)b * Tq + t0 + ty + 8 * kk) * DINq + i0 + tx;
        __nv_bfloat16 h, l;
        split1(v, h, l);
        xh[idx] = h; xl[idx] = l;
    }
}

// ---------------------------------------------------------------------------
// Weight split: 22 fp32 matrices -> g_wh / g_wl
// ---------------------------------------------------------------------------
struct WPtrs { const float* p[22]; };

__global__ __launch_bounds__(256)
void convw_kernel(WPtrs wp, __nv_bfloat16* __restrict__ wh, __nv_bfloat16* __restrict__ wl)
{
    const int idx = blockIdx.x * 256 + threadIdx.x;
    int off = 0;
#pragma unroll
    for (int m = 0; m < 22; m++) {
        const int sz = (m == 0) ? 262144 : ((m == 21) ? NCq * DMq : 65536);
        if (idx < off + sz) {
            __nv_bfloat16 h, l;
            split1(wp.p[m][idx - off], h, l);
            wh[idx] = h; wl[idx] = l;
            return;
        }
        off += sz;
    }
}

// ---------------------------------------------------------------------------
// Dilated 3-tap softmax attention + ReLU on hi/lo arrays, 4 channels/thread
// ---------------------------------------------------------------------------
__device__ __forceinline__ void load4(const __nv_bfloat16* __restrict__ h,
                                      const __nv_bfloat16* __restrict__ l,
                                      size_t e, float (&o)[4])
{
    const __nv_bfloat162 h0 = *(const __nv_bfloat162*)(h + e);
    const __nv_bfloat162 h1 = *(const __nv_bfloat162*)(h + e + 2);
    const __nv_bfloat162 l0 = *(const __nv_bfloat162*)(l + e);
    const __nv_bfloat162 l1 = *(const __nv_bfloat162*)(l + e + 2);
    o[0] = __bfloat162float(h0.x) + __bfloat162float(l0.x);
    o[1] = __bfloat162float(h0.y) + __bfloat162float(l0.y);
    o[2] = __bfloat162float(h1.x) + __bfloat162float(l1.x);
    o[3] = __bfloat162float(h1.y) + __bfloat162float(l1.y);
}

__device__ __forceinline__ float attn1(float q, float k0, float k1, float k2,
                                       float v0, float v1, float v2)
{
    const float s0 = q * k0, s1 = q * k1, s2 = q * k2;
    const float mx = fmaxf(s0, fmaxf(s1, s2));
    const float e0 = __expf(s0 - mx), e1 = __expf(s1 - mx), e2 = __expf(s2 - mx);
    return fmaxf((e0 * v0 + e1 * v1 + e2 * v2) / (e0 + e1 + e2), 0.f);
}

__global__ __launch_bounds__(256)
void attn_kernel(const __nv_bfloat16* __restrict__ qh, const __nv_bfloat16* __restrict__ ql,
                 const __nv_bfloat16* __restrict__ kh, const __nv_bfloat16* __restrict__ kl,
                 const __nv_bfloat16* __restrict__ vh, const __nv_bfloat16* __restrict__ vl,
                 __nv_bfloat16* __restrict__ hh, __nv_bfloat16* __restrict__ hl, int d)
{
    const size_t gid = (size_t)blockIdx.x * 256 + threadIdx.x;  // 4-channel unit
    const int t = (int)((gid >> 6) & (Tq - 1));
    const size_t e = gid * 4;
    const long long off = (long long)d * DMq;

    float q[4], k1[4], v1[4];
    load4(qh, ql, e, q);
    load4(kh, kl, e, k1);
    load4(vh, vl, e, v1);
    float k0[4] = {0, 0, 0, 0}, v0[4] = {0, 0, 0, 0};
    float k2[4] = {0, 0, 0, 0}, v2[4] = {0, 0, 0, 0};
    if (t - d >= 0) { load4(kh, kl, e - off, k0); load4(vh, vl, e - off, v0); }
    if (t + d < Tq) { load4(kh, kl, e + off, k2); load4(vh, vl, e + off, v2); }

    __nv_bfloat16 rh[4], rl[4];
#pragma unroll
    for (int c = 0; c < 4; c++) {
        const float r = attn1(q[c], k0[c], k1[c], k2[c], v0[c], v1[c], v2[c]);
        split1(r, rh[c], rl[c]);
    }
    *(__nv_bfloat162*)(hh + e)     = __nv_bfloat162(rh[0], rh[1]);
    *(__nv_bfloat162*)(hh + e + 2) = __nv_bfloat162(rh[2], rh[3]);
    *(__nv_bfloat162*)(hl + e)     = __nv_bfloat162(rl[0], rl[1]);
    *(__nv_bfloat162*)(hl + e + 2) = __nv_bfloat162(rl[2], rl[3]);
}

// ---------------------------------------------------------------------------
// Launch
// ---------------------------------------------------------------------------
extern "C" void kernel_launch(void* const* d_in, const int* in_sizes, int n_in,
                              void* d_out, int out_size)
{
    const float* x    = (const float*)d_in[0];
    const float* mask = (const float*)d_in[1];
    const float* b0b  = (const float*)d_in[3];
    const float* b6b  = (const float*)d_in[30];

    __nv_bfloat16 *xh, *xl, *oh, *ol, *qh, *ql, *kh, *kl, *vh, *vl, *hh, *hl, *wh, *wl;
    cudaGetSymbolAddress((void**)&xh, g_xh);  cudaGetSymbolAddress((void**)&xl, g_xl);
    cudaGetSymbolAddress((void**)&oh, g_oh);  cudaGetSymbolAddress((void**)&ol, g_ol);
    cudaGetSymbolAddress((void**)&qh, g_qh);  cudaGetSymbolAddress((void**)&ql, g_ql);
    cudaGetSymbolAddress((void**)&kh, g_kh);  cudaGetSymbolAddress((void**)&kl, g_kl);
    cudaGetSymbolAddress((void**)&vh, g_vh);  cudaGetSymbolAddress((void**)&vl, g_vl);
    cudaGetSymbolAddress((void**)&hh, g_hh);  cudaGetSymbolAddress((void**)&hl, g_hl);
    cudaGetSymbolAddress((void**)&wh, g_wh);  cudaGetSymbolAddress((void**)&wl, g_wl);

    cudaFuncSetAttribute(gemm_mma<1, DINq, DMq>, cudaFuncAttributeMaxDynamicSharedMemorySize, SMEM_TOT);
    cudaFuncSetAttribute(gemm_mma<0, DMq,  DMq>, cudaFuncAttributeMaxDynamicSharedMemorySize, SMEM_TOT);
    cudaFuncSetAttribute(gemm_mma<2, DMq,  DMq>, cudaFuncAttributeMaxDynamicSharedMemorySize, SMEM_TOT);
    cudaFuncSetAttribute(gemm_mma<3, DMq,  NCq>, cudaFuncAttributeMaxDynamicSharedMemorySize, SMEM_TOT);

    // split weights
    WPtrs wp;
    wp.p[0] = (const float*)d_in[2];
    for (int l = 0; l < 5; l++) {
        wp.p[1 + 4 * l + 0] = (const float*)d_in[4 + 5 * l + 0];
        wp.p[1 + 4 * l + 1] = (const float*)d_in[4 + 5 * l + 1];
        wp.p[1 + 4 * l + 2] = (const float*)d_in[4 + 5 * l + 2];
        wp.p[1 + 4 * l + 3] = (const float*)d_in[4 + 5 * l + 3];
    }
    wp.p[21] = (const float*)d_in[29];
    convw_kernel<<<W_TOTAL / 256, 256>>>(wp, wh, wl);

    // transpose + split input
    xpose_kernel<<<dim3(Tq / 32, DINq / 32, Bq), 256>>>(x, xh, xl);

    const dim3 thr(256);
    const dim3 g_dm(Tq / 128, DMq / 128, Bq);
    const dim3 g_nc(Tq / 128, (NCq + 127) / 128, Bq);
    const int  g_at = (Bq * Tq * DMq / 4) / 256;

    // input GEMM: out = b0w @ xt + b0b
    gemm_mma<1, DINq, DMq><<<g_dm, thr, SMEM_TOT>>>(
        wh + W_B0, wl + W_B0, xh, xl, b0b, nullptr, nullptr, nullptr, oh, ol, nullptr);

    const int dils[5] = {1, 2, 4, 8, 16};
    for (int l = 0; l < 5; l++) {
        const float* bb = (const float*)d_in[4 + 5 * l + 4];
        const int wq = W_L0 + l * W_PERL;
        const int wk = wq + 65536;
        const int wv = wk + 65536;
        const int bw = wv + 65536;

        gemm_mma<0, DMq, DMq><<<g_dm, thr, SMEM_TOT>>>(
            wh + wq, wl + wq, oh, ol, nullptr, nullptr, nullptr, nullptr, qh, ql, nullptr);
        gemm_mma<0, DMq, DMq><<<g_dm, thr, SMEM_TOT>>>(
            wh + wk, wl + wk, oh, ol, nullptr, nullptr, nullptr, nullptr, kh, kl, nullptr);
        gemm_mma<0, DMq, DMq><<<g_dm, thr, SMEM_TOT>>>(
            wh + wv, wl + wv, oh, ol, nullptr, nullptr, nullptr, nullptr, vh, vl, nullptr);

        attn_kernel<<<g_at, thr>>>(qh, ql, kh, kl, vh, vl, hh, hl, dils[l]);

        gemm_mma<2, DMq, DMq><<<g_dm, thr, SMEM_TOT>>>(
            wh + bw, wl + bw, hh, hl, bb, mask, oh, ol, oh, ol, nullptr);
    }

    // final: (b6w @ out + b6b) * mask -> fp32 [B, NC, T]
    gemm_mma<3, DMq, NCq><<<g_nc, thr, SMEM_TOT>>>(
        wh + W_B6, wl + W_B6, oh, ol, b6b, mask, nullptr, nullptr, nullptr, nullptr, (float*)d_out);
}

// round 5
// speedup vs baseline: 1.8391x; 1.0311x over previous
#include <cuda_runtime.h>
#include <cuda_bf16.h>

#define Bq   8
#define Tq   4096
#define DINq 1024
#define DMq  256
#define NCq  157

// ---------------------------------------------------------------------------
// Scratch: bf16 hi/lo arrays, activations in [B, T, C] (K-major for MMA B op)
// value = float(hi) + float(lo)  (error ~2^-18 relative)
// qkv is fused: [B, T, 768] with q at c, k at c+256, v at c+512
// ---------------------------------------------------------------------------
__device__ __nv_bfloat16 g_xh  [Bq * Tq * DINq];
__device__ __nv_bfloat16 g_xl  [Bq * Tq * DINq];
__device__ __nv_bfloat16 g_oh  [Bq * Tq * DMq];
__device__ __nv_bfloat16 g_ol  [Bq * Tq * DMq];
__device__ __nv_bfloat16 g_qkvh[Bq * Tq * 3 * DMq];
__device__ __nv_bfloat16 g_qkvl[Bq * Tq * 3 * DMq];
__device__ __nv_bfloat16 g_hh  [Bq * Tq * DMq];
__device__ __nv_bfloat16 g_hl  [Bq * Tq * DMq];

// Weights split hi/lo, packed: b0w(256x1024), per layer wq|wk|wv|bw (each 256x256), b6w(157x256)
#define W_B0    0
#define W_L0    262144
#define W_PERL  (4 * 65536)
#define W_B6    (262144 + 5 * W_PERL)
#define W_TOTAL (W_B6 + NCq * DMq)
__device__ __nv_bfloat16 g_wh[W_TOTAL];
__device__ __nv_bfloat16 g_wl[W_TOTAL];

// ---------------------------------------------------------------------------
// Helpers
// ---------------------------------------------------------------------------
__device__ __forceinline__ unsigned smem_u32(const void* p) {
    unsigned a;
    asm("{ .reg .u64 t; cvta.to.shared.u64 t, %1; cvt.u32.u64 %0, t; }" : "=r"(a) : "l"(p));
    return a;
}
__device__ __forceinline__ void split1(float v, __nv_bfloat16& h, __nv_bfloat16& l) {
    h = __float2bfloat16_rn(v);
    l = __float2bfloat16_rn(v - __bfloat162float(h));
}
__device__ __forceinline__ void ldmat4(unsigned (&r)[4], unsigned addr) {
    asm volatile("ldmatrix.sync.aligned.m8n8.x4.shared.b16 {%0,%1,%2,%3}, [%4];"
                 : "=r"(r[0]), "=r"(r[1]), "=r"(r[2]), "=r"(r[3]) : "r"(addr));
}
__device__ __forceinline__ void mma16816(float (&c)[4], const unsigned (&a)[4],
                                         unsigned b0, unsigned b1) {
    asm volatile(
        "mma.sync.aligned.m16n8k16.row.col.f32.bf16.bf16.f32 "
        "{%0,%1,%2,%3}, {%4,%5,%6,%7}, {%8,%9}, {%0,%1,%2,%3};"
        : "+f"(c[0]), "+f"(c[1]), "+f"(c[2]), "+f"(c[3])
        : "r"(a[0]), "r"(a[1]), "r"(a[2]), "r"(a[3]), "r"(b0), "r"(b1));
}
__device__ __forceinline__ void cp16(unsigned saddr, const void* gaddr, int srcsz) {
    asm volatile("cp.async.ca.shared.global [%0], [%1], 16, %2;"
                 :: "r"(saddr), "l"(gaddr), "r"(srcsz) : "memory");
}
#define CP_COMMIT() asm volatile("cp.async.commit_group;" ::: "memory")
#define CP_WAIT1()  asm volatile("cp.async.wait_group 1;" ::: "memory")

// ---------------------------------------------------------------------------
// GEMM: D[o,t] = sum_i W[o,i] * Act[b,t,i]   (split-bf16 x3, mma.sync)
// Block 128(M=o) x 128(N=t), K-chunk 32, 256 threads (8 warps, 4m x 2n),
// warp tile 32x64. cp.async 3-stage pipeline, 64B stride + XOR swizzle.
// EPI: 0 plain, 1 +bias, 2 (resid+D+bias)*mask -> bf16 hi/lo [b,t,o] stride OSTR
//      3 (D+bias)*mask -> fp32 [b,o,t]
// ---------------------------------------------------------------------------
#define TILE_P   8192               // one 128x32 bf16 part (64B stride)
#define STAGE    32768              // A.hi A.lo B.hi B.lo
#define SMEM_TOT 98304              // 3 stages

template <int EPI, int KTOT, int OROWS, int OSTR>
__global__ void __launch_bounds__(256, 2)
gemm_mma(const __nv_bfloat16* __restrict__ Whi, const __nv_bfloat16* __restrict__ Wlo,
         const __nv_bfloat16* __restrict__ Ahi, const __nv_bfloat16* __restrict__ Alo,
         const float* __restrict__ bias, const float* __restrict__ mask,
         const __nv_bfloat16* __restrict__ Rhi, const __nv_bfloat16* __restrict__ Rlo,
         __nv_bfloat16* __restrict__ Ohi, __nv_bfloat16* __restrict__ Olo,
         float* __restrict__ OF)
{
    extern __shared__ char smem[];
    const unsigned sb = smem_u32(smem);
    const int tid  = threadIdx.x;
    const int lane = tid & 31, wid = tid >> 5;
    const int bT = blockIdx.x * 128;
    const int bO = blockIdx.y * 128;
    const int b  = blockIdx.z;
    const int m0 = (wid & 3) * 32;
    const int n0 = (wid >> 2) * 64;

    constexpr bool GUARDA = (OROWS & 127) != 0;
    constexpr int NCH = KTOT / 32;

    const __nv_bfloat16* Bh = Ahi + ((size_t)b * Tq + bT) * KTOT;
    const __nv_bfloat16* Bl = Alo + ((size_t)b * Tq + bT) * KTOT;

    // ldmatrix per-thread swizzled offsets (64B stride, chunk ^= (row>>1)&3)
    const int raA  = lane & 15;
    const int xorA = (raA >> 1) & 3;
    const int laA[2] = { raA * 64 + ((((lane >> 4)    ) ^ xorA) << 4),
                         raA * 64 + ((((lane >> 4) + 2) ^ xorA) << 4) };
    const int matv = lane >> 3;
    const int rbB  = (lane & 7) + ((matv >> 1) * 8);
    const int xorB = (rbB >> 1) & 3;
    const int lbB[2] = { rbB * 64 + ((((matv & 1)    ) ^ xorB) << 4),
                         rbB * 64 + ((((matv & 1) + 2) ^ xorB) << 4) };

    float acc[2][8][4];
#pragma unroll
    for (int i = 0; i < 2; i++)
#pragma unroll
        for (int j = 0; j < 8; j++)
#pragma unroll
            for (int l = 0; l < 4; l++) acc[i][j][l] = 0.f;

    // ---- async tile issue (always commits exactly one group) ----
    auto issue = [&](int ch, int stg) {
        if (ch < NCH) {
            const int k0 = ch * 32;
            const unsigned st = sb + stg * STAGE;
#pragma unroll
            for (int i = 0; i < 2; i++) {
                const int task = i * 256 + tid;
                const int row = task >> 2, c = task & 3;
                const unsigned soff = (unsigned)(row * 64 + ((c ^ ((row >> 1) & 3)) << 4));
                int asz = 16;
                size_t aoff = (size_t)(bO + row) * KTOT + k0 + c * 8;
                if (GUARDA && (bO + row >= OROWS)) { asz = 0; aoff = 0; }
                cp16(st + soff,              Whi + aoff, asz);
                cp16(st + TILE_P + soff,     Wlo + aoff, asz);
                const size_t boff = (size_t)row * KTOT + k0 + c * 8;
                cp16(st + 2 * TILE_P + soff, Bh + boff, 16);
                cp16(st + 3 * TILE_P + soff, Bl + boff, 16);
            }
        }
        CP_COMMIT();
    };

    issue(0, 0);
    issue(1, 1);

    int cs = 0, is = 2;
#pragma unroll 1
    for (int ch = 0; ch < NCH; ch++) {
        CP_WAIT1();
        __syncthreads();
        issue(ch + 2, is);
        is = (is == 2) ? 0 : is + 1;

        const unsigned Ah_ = sb + cs * STAGE;
        const unsigned Al_ = Ah_ + TILE_P;
        const unsigned Bh_ = Ah_ + 2 * TILE_P;
        const unsigned Bl_ = Ah_ + 3 * TILE_P;
        cs = (cs == 2) ? 0 : cs + 1;

#pragma unroll
        for (int kk = 0; kk < 2; kk++) {
            unsigned ah[2][4], al[2][4];
            ldmat4(ah[0], Ah_ + (m0     ) * 64 + laA[kk]);
            ldmat4(ah[1], Ah_ + (m0 + 16) * 64 + laA[kk]);
            ldmat4(al[0], Al_ + (m0     ) * 64 + laA[kk]);
            ldmat4(al[1], Al_ + (m0 + 16) * 64 + laA[kk]);
#pragma unroll
            for (int nt2 = 0; nt2 < 4; nt2++) {
                unsigned bh[4], bl[4];
                ldmat4(bh, Bh_ + (n0 + nt2 * 16) * 64 + lbB[kk]);
                ldmat4(bl, Bl_ + (n0 + nt2 * 16) * 64 + lbB[kk]);
                mma16816(acc[0][nt2 * 2 + 0], ah[0], bh[0], bh[1]);
                mma16816(acc[0][nt2 * 2 + 1], ah[0], bh[2], bh[3]);
                mma16816(acc[1][nt2 * 2 + 0], ah[1], bh[0], bh[1]);
                mma16816(acc[1][nt2 * 2 + 1], ah[1], bh[2], bh[3]);
                mma16816(acc[0][nt2 * 2 + 0], ah[0], bl[0], bl[1]);
                mma16816(acc[0][nt2 * 2 + 1], ah[0], bl[2], bl[3]);
                mma16816(acc[1][nt2 * 2 + 0], ah[1], bl[0], bl[1]);
                mma16816(acc[1][nt2 * 2 + 1], ah[1], bl[2], bl[3]);
                mma16816(acc[0][nt2 * 2 + 0], al[0], bh[0], bh[1]);
                mma16816(acc[0][nt2 * 2 + 1], al[0], bh[2], bh[3]);
                mma16816(acc[1][nt2 * 2 + 0], al[1], bh[0], bh[1]);
                mma16816(acc[1][nt2 * 2 + 1], al[1], bh[2], bh[3]);
            }
        }
    }

    // ---- epilogue ----
    const int g = lane >> 2, tig = lane & 3;
#pragma unroll
    for (int mi = 0; mi < 2; mi++) {
#pragma unroll
        for (int pr = 0; pr < 2; pr++) {
            const int o = bO + m0 + mi * 16 + g + pr * 8;
            float bs = 0.f;
            if (EPI >= 1) bs = (!GUARDA || o < OROWS) ? bias[o] : 0.f;
#pragma unroll
            for (int nt = 0; nt < 8; nt++) {
                const int t = bT + n0 + nt * 8 + 2 * tig;
                float v0 = acc[mi][nt][pr * 2 + 0] + bs;
                float v1 = acc[mi][nt][pr * 2 + 1] + bs;
                if (EPI == 3) {
                    if (!GUARDA || o < OROWS) {
                        const float mk0 = mask[(size_t)b * Tq + t];
                        const float mk1 = mask[(size_t)b * Tq + t + 1];
                        *(float2*)(OF + ((size_t)b * OROWS + o) * Tq + t) =
                            make_float2(v0 * mk0, v1 * mk1);
                    }
                } else {
                    const size_t i0 = ((size_t)b * Tq + t) * OSTR + o;
                    if (EPI == 2) {
                        const float mk0 = mask[(size_t)b * Tq + t];
                        const float mk1 = mask[(size_t)b * Tq + t + 1];
                        float r0 = __bfloat162float(Rhi[i0]) + __bfloat162float(Rlo[i0]);
                        float r1 = __bfloat162float(Rhi[i0 + OSTR]) + __bfloat162float(Rlo[i0 + OSTR]);
                        v0 = (r0 + v0) * mk0;
                        v1 = (r1 + v1) * mk1;
                    }
                    __nv_bfloat16 h0, l0, h1, l1;
                    split1(v0, h0, l0);
                    split1(v1, h1, l1);
                    Ohi[i0] = h0; Olo[i0] = l0;
                    Ohi[i0 + OSTR] = h1; Olo[i0 + OSTR] = l1;
                }
            }
        }
    }
}

// ---------------------------------------------------------------------------
// x transpose + split: [B, DIN, T] fp32 -> [B, T, DIN] bf16 hi/lo
// ---------------------------------------------------------------------------
__global__ __launch_bounds__(256)
void xpose_kernel(const float* __restrict__ x,
                  __nv_bfloat16* __restrict__ xh, __nv_bfloat16* __restrict__ xl)
{
    __shared__ float s[32][33];
    const int t0 = blockIdx.x * 32, i0 = blockIdx.y * 32, b = blockIdx.z;
    const int tx = threadIdx.x & 31, ty = threadIdx.x >> 5;
    const float* xb = x + (size_t)b * DINq * Tq;
#pragma unroll
    for (int kk = 0; kk < 4; kk++)
        s[ty + 8 * kk][tx] = xb[(size_t)(i0 + ty + 8 * kk) * Tq + t0 + tx];
    __syncthreads();
#pragma unroll
    for (int kk = 0; kk < 4; kk++) {
        const float v = s[tx][ty + 8 * kk];
        const size_t idx = ((size_t)b * Tq + t0 + ty + 8 * kk) * DINq + i0 + tx;
        __nv_bfloat16 h, l;
        split1(v, h, l);
        xh[idx] = h; xl[idx] = l;
    }
}

// ---------------------------------------------------------------------------
// Weight split
// ---------------------------------------------------------------------------
struct WPtrs { const float* p[22]; };

__global__ __launch_bounds__(256)
void convw_kernel(WPtrs wp, __nv_bfloat16* __restrict__ wh, __nv_bfloat16* __restrict__ wl)
{
    const int idx = blockIdx.x * 256 + threadIdx.x;
    int off = 0;
#pragma unroll
    for (int m = 0; m < 22; m++) {
        const int sz = (m == 0) ? 262144 : ((m == 21) ? NCq * DMq : 65536);
        if (idx < off + sz) {
            __nv_bfloat16 h, l;
            split1(wp.p[m][idx - off], h, l);
            wh[idx] = h; wl[idx] = l;
            return;
        }
        off += sz;
    }
}

// ---------------------------------------------------------------------------
// Dilated 3-tap softmax attention + ReLU, reading fused qkv [B,T,768]
// ---------------------------------------------------------------------------
__device__ __forceinline__ void load4(const __nv_bfloat16* __restrict__ h,
                                      const __nv_bfloat16* __restrict__ l,
                                      size_t e, float (&o)[4])
{
    const __nv_bfloat162 h0 = *(const __nv_bfloat162*)(h + e);
    const __nv_bfloat162 h1 = *(const __nv_bfloat162*)(h + e + 2);
    const __nv_bfloat162 l0 = *(const __nv_bfloat162*)(l + e);
    const __nv_bfloat162 l1 = *(const __nv_bfloat162*)(l + e + 2);
    o[0] = __bfloat162float(h0.x) + __bfloat162float(l0.x);
    o[1] = __bfloat162float(h0.y) + __bfloat162float(l0.y);
    o[2] = __bfloat162float(h1.x) + __bfloat162float(l1.x);
    o[3] = __bfloat162float(h1.y) + __bfloat162float(l1.y);
}

__device__ __forceinline__ float attn1(float q, float k0, float k1, float k2,
                                       float v0, float v1, float v2)
{
    const float s0 = q * k0, s1 = q * k1, s2 = q * k2;
    const float mx = fmaxf(s0, fmaxf(s1, s2));
    const float e0 = __expf(s0 - mx), e1 = __expf(s1 - mx), e2 = __expf(s2 - mx);
    return fmaxf((e0 * v0 + e1 * v1 + e2 * v2) / (e0 + e1 + e2), 0.f);
}

__global__ __launch_bounds__(256)
void attn_kernel(const __nv_bfloat16* __restrict__ qkvh, const __nv_bfloat16* __restrict__ qkvl,
                 __nv_bfloat16* __restrict__ hh, __nv_bfloat16* __restrict__ hl, int d)
{
    const size_t gid = (size_t)blockIdx.x * 256 + threadIdx.x;   // 4-channel unit
    const int c4 = (int)(gid & 63);
    const int t  = (int)((gid >> 6) & (Tq - 1));
    const int b  = (int)(gid >> 18);
    const size_t rq = ((size_t)b * Tq + t) * 768 + c4 * 4;
    const long long off = (long long)d * 768;

    float q[4], k1[4], v1[4];
    load4(qkvh, qkvl, rq,       q);
    load4(qkvh, qkvl, rq + 256, k1);
    load4(qkvh, qkvl, rq + 512, v1);
    float k0[4] = {0, 0, 0, 0}, v0[4] = {0, 0, 0, 0};
    float k2[4] = {0, 0, 0, 0}, v2[4] = {0, 0, 0, 0};
    if (t - d >= 0) { load4(qkvh, qkvl, rq + 256 - off, k0); load4(qkvh, qkvl, rq + 512 - off, v0); }
    if (t + d < Tq) { load4(qkvh, qkvl, rq + 256 + off, k2); load4(qkvh, qkvl, rq + 512 + off, v2); }

    const size_t e = ((size_t)b * Tq + t) * DMq + c4 * 4;
    __nv_bfloat16 rh[4], rl[4];
#pragma unroll
    for (int c = 0; c < 4; c++) {
        const float r = attn1(q[c], k0[c], k1[c], k2[c], v0[c], v1[c], v2[c]);
        split1(r, rh[c], rl[c]);
    }
    *(__nv_bfloat162*)(hh + e)     = __nv_bfloat162(rh[0], rh[1]);
    *(__nv_bfloat162*)(hh + e + 2) = __nv_bfloat162(rh[2], rh[3]);
    *(__nv_bfloat162*)(hl + e)     = __nv_bfloat162(rl[0], rl[1]);
    *(__nv_bfloat162*)(hl + e + 2) = __nv_bfloat162(rl[2], rl[3]);
}

// ---------------------------------------------------------------------------
// Launch
// ---------------------------------------------------------------------------
extern "C" void kernel_launch(void* const* d_in, const int* in_sizes, int n_in,
                              void* d_out, int out_size)
{
    const float* x    = (const float*)d_in[0];
    const float* mask = (const float*)d_in[1];
    const float* b0b  = (const float*)d_in[3];
    const float* b6b  = (const float*)d_in[30];

    __nv_bfloat16 *xh, *xl, *oh, *ol, *qkvh, *qkvl, *hh, *hl, *wh, *wl;
    cudaGetSymbolAddress((void**)&xh, g_xh);      cudaGetSymbolAddress((void**)&xl, g_xl);
    cudaGetSymbolAddress((void**)&oh, g_oh);      cudaGetSymbolAddress((void**)&ol, g_ol);
    cudaGetSymbolAddress((void**)&qkvh, g_qkvh);  cudaGetSymbolAddress((void**)&qkvl, g_qkvl);
    cudaGetSymbolAddress((void**)&hh, g_hh);      cudaGetSymbolAddress((void**)&hl, g_hl);
    cudaGetSymbolAddress((void**)&wh, g_wh);      cudaGetSymbolAddress((void**)&wl, g_wl);

    cudaFuncSetAttribute(gemm_mma<1, DINq, DMq, DMq>,     cudaFuncAttributeMaxDynamicSharedMemorySize, SMEM_TOT);
    cudaFuncSetAttribute(gemm_mma<0, DMq, 3 * DMq, 3 * DMq>, cudaFuncAttributeMaxDynamicSharedMemorySize, SMEM_TOT);
    cudaFuncSetAttribute(gemm_mma<2, DMq, DMq, DMq>,      cudaFuncAttributeMaxDynamicSharedMemorySize, SMEM_TOT);
    cudaFuncSetAttribute(gemm_mma<3, DMq, NCq, DMq>,      cudaFuncAttributeMaxDynamicSharedMemorySize, SMEM_TOT);

    // split weights
    WPtrs wp;
    wp.p[0] = (const float*)d_in[2];
    for (int l = 0; l < 5; l++) {
        wp.p[1 + 4 * l + 0] = (const float*)d_in[4 + 5 * l + 0];
        wp.p[1 + 4 * l + 1] = (const float*)d_in[4 + 5 * l + 1];
        wp.p[1 + 4 * l + 2] = (const float*)d_in[4 + 5 * l + 2];
        wp.p[1 + 4 * l + 3] = (const float*)d_in[4 + 5 * l + 3];
    }
    wp.p[21] = (const float*)d_in[29];
    convw_kernel<<<W_TOTAL / 256, 256>>>(wp, wh, wl);

    // transpose + split input
    xpose_kernel<<<dim3(Tq / 32, DINq / 32, Bq), 256>>>(x, xh, xl);

    const dim3 thr(256);
    const dim3 g_dm (Tq / 128, DMq / 128, Bq);             // (32, 2, 8)
    const dim3 g_qkv(Tq / 128, 3 * DMq / 128, Bq);         // (32, 6, 8)
    const dim3 g_nc (Tq / 128, (NCq + 127) / 128, Bq);     // (32, 2, 8)
    const int  g_at = (Bq * Tq * 64) / 256;                // 8192

    // input GEMM: out = b0w @ xt + b0b
    gemm_mma<1, DINq, DMq, DMq><<<g_dm, thr, SMEM_TOT>>>(
        wh + W_B0, wl + W_B0, xh, xl, b0b, nullptr, nullptr, nullptr, oh, ol, nullptr);

    const int dils[5] = {1, 2, 4, 8, 16};
    for (int l = 0; l < 5; l++) {
        const float* bb = (const float*)d_in[4 + 5 * l + 4];
        const int wqkv = W_L0 + l * W_PERL;          // wq|wk|wv stacked (768x256)
        const int bw   = wqkv + 3 * 65536;

        // fused QKV GEMM -> qkv [b,t,768]
        gemm_mma<0, DMq, 3 * DMq, 3 * DMq><<<g_qkv, thr, SMEM_TOT>>>(
            wh + wqkv, wl + wqkv, oh, ol, nullptr, nullptr, nullptr, nullptr,
            qkvh, qkvl, nullptr);

        attn_kernel<<<g_at, thr>>>(qkvh, qkvl, hh, hl, dils[l]);

        // out = (out + bw@h + bb) * mask
        gemm_mma<2, DMq, DMq, DMq><<<g_dm, thr, SMEM_TOT>>>(
            wh + bw, wl + bw, hh, hl, bb, mask, oh, ol, oh, ol, nullptr);
    }

    // final: (b6w @ out + b6b) * mask -> fp32 [B, NC, T]
    gemm_mma<3, DMq, NCq, DMq><<<g_nc, thr, SMEM_TOT>>>(
        wh + W_B6, wl + W_B6, oh, ol, b6b, mask, nullptr, nullptr, nullptr, nullptr, (float*)d_out);
}